// round 1
// baseline (speedup 1.0000x reference)
#include <cuda_runtime.h>
#include <cstdint>

// ArcFace forward:
//   out[b,c] = S * logits[b,c]                          (c != labels[b])
//   out[b,labels[b]] = S * cos(arccos(x) + MARGIN)
//                    = S * (x*cos(m) - sin(m)*sqrt(1-x^2))
// S = 64, m = 0.5. B=256, C=100000 (25.6M fp32) -> HBM-bound stream.

static constexpr float S_SCALE = 64.0f;
static constexpr float COS_M   = 0.8775825618903728f;  // cos(0.5)
static constexpr float SIN_M   = 0.4794255386042030f;  // sin(0.5)

// ---------------------------------------------------------------------------
// Pass 1: out = S * logits, vectorized float4. 25.6M elements / 4 = 6.4M vec4.
// ---------------------------------------------------------------------------
__global__ void __launch_bounds__(256)
scale_kernel(const float4* __restrict__ in, float4* __restrict__ out, int n4) {
    int i = blockIdx.x * blockDim.x + threadIdx.x;
    if (i < n4) {
        float4 v = __ldg(&in[i]);
        v.x *= S_SCALE;
        v.y *= S_SCALE;
        v.z *= S_SCALE;
        v.w *= S_SCALE;
        out[i] = v;
    }
}

// ---------------------------------------------------------------------------
// Pass 2: fix the B target entries. One block of B threads.
// Runtime label-dtype sniff: if the buffer is int64 (little-endian, labels
// >= 0 and < 2^31), every odd int32 word is zero. If it's int32, the odd
// words are labels themselves (uniform in [0,100000)) and essentially never
// all zero. Scanning int32 indices [1,3,...,2*(B/2)-1] is in-bounds for BOTH
// layouts (int32 buffer has B words, int64 buffer has 2B words).
// ---------------------------------------------------------------------------
__global__ void __launch_bounds__(256)
fixup_kernel(const float* __restrict__ logits,
             const int32_t* __restrict__ labels_i32,  // raw view of labels buffer
             float* __restrict__ out,
             int B, int C) {
    __shared__ int any_odd_nonzero;
    if (threadIdx.x == 0) any_odd_nonzero = 0;
    __syncthreads();

    int tid = threadIdx.x;
    // threads 0..B/2-1 check odd words (high halves if int64)
    if (tid < B / 2) {
        if (labels_i32[2 * tid + 1] != 0) atomicOr(&any_odd_nonzero, 1);
    }
    __syncthreads();

    bool is_int64 = (any_odd_nonzero == 0);

    if (tid < B) {
        long long lab;
        if (is_int64) {
            lab = reinterpret_cast<const long long*>(labels_i32)[tid];
        } else {
            lab = (long long)labels_i32[tid];
        }
        if (lab >= 0 && lab < (long long)C) {
            size_t idx = (size_t)tid * (size_t)C + (size_t)lab;
            float x = logits[idx];
            float s = sqrtf(fmaxf(1.0f - x * x, 0.0f));
            out[idx] = S_SCALE * (x * COS_M - SIN_M * s);
        }
        // lab == -1: out already holds S * x from pass 1 (reference identity)
    }
}

extern "C" void kernel_launch(void* const* d_in, const int* in_sizes, int n_in,
                              void* d_out, int out_size) {
    const float* logits = (const float*)d_in[0];
    const int32_t* labels = (const int32_t*)d_in[1];
    float* out = (float*)d_out;

    int total = in_sizes[0];      // B*C = 25,600,000
    int B = in_sizes[1];          // 256
    int C = total / B;            // 100,000

    // total is divisible by 4 (25.6M)
    int n4 = total / 4;
    int threads = 256;
    int blocks = (n4 + threads - 1) / threads;
    scale_kernel<<<blocks, threads>>>((const float4*)logits, (float4*)out, n4);
    fixup_kernel<<<1, 256>>>(logits, labels, out, B, C);
}

// round 2
// speedup vs baseline: 1.1052x; 1.1052x over previous
#include <cuda_runtime.h>
#include <cstdint>

// ArcFace forward, fused single pass:
//   out[b,c] = S * logits[b,c]                         (c != labels[b])
//   out[b,lab] = S * (x*cos(m) - sin(m)*sqrt(1-x^2))   (closed form of cos(arccos(x)+m))
// B=256, C=100000 (divisible by 4 -> each float4 is within one row).
// Pure HBM stream: 102.4MB read + 102.4MB write.

static constexpr float S_SCALE = 64.0f;
static constexpr float COS_M   = 0.8775825618903728f;  // cos(0.5)
static constexpr float SIN_M   = 0.4794255386042030f;  // sin(0.5)

__device__ __forceinline__ float arcface_fix(float x) {
    float s = sqrtf(fmaxf(1.0f - x * x, 0.0f));
    return S_SCALE * (x * COS_M - SIN_M * s);
}

// Process one float4: scale by S, patch the target lane if the label falls here.
__device__ __forceinline__ void process_vec(
    const float4* __restrict__ in, float4* __restrict__ out,
    const int32_t* __restrict__ labels_i32, bool is64,
    int i, int c4)
{
    float4 v = __ldcs(&in[i]);
    float4 o;
    o.x = v.x * S_SCALE;
    o.y = v.y * S_SCALE;
    o.z = v.z * S_SCALE;
    o.w = v.w * S_SCALE;

    int b    = i / c4;            // row
    int col4 = i - b * c4;        // vec4-column within row

    // label for this row: broadcast within warp, L1-cached
    long long lab = is64 ? reinterpret_cast<const long long*>(labels_i32)[b]
                         : (long long)labels_i32[b];

    if (lab >= 0 && (int)(lab >> 2) == col4) {      // target lane lives in this vec4
        int lane = (int)(lab & 3);
        switch (lane) {
            case 0: o.x = arcface_fix(v.x); break;
            case 1: o.y = arcface_fix(v.y); break;
            case 2: o.z = arcface_fix(v.z); break;
            default: o.w = arcface_fix(v.w); break;
        }
    }
    __stcs(&out[i], o);
}

__global__ void __launch_bounds__(256)
arcface_fused_kernel(const float4* __restrict__ in,
                     const int32_t* __restrict__ labels_i32,
                     float4* __restrict__ out,
                     int n4, int c4, int half)
{
    // Label-dtype sniff (int64 vs int32 buffer), one thread per block.
    // For little-endian int64 labels in [0, 2^31): all odd words are 0.
    // For int32 labels uniform in [0,100000): odd words 1,3,5,7 all zero
    // has probability ~1e-20. Both layouts have >= 8 words for B=256.
    __shared__ int s_is64;
    if (threadIdx.x == 0) {
        int odd = labels_i32[1] | labels_i32[3] | labels_i32[5] | labels_i32[7];
        s_is64 = (odd == 0);
    }
    __syncthreads();
    bool is64 = (s_is64 != 0);

    int i = blockIdx.x * blockDim.x + threadIdx.x;
    if (i < half)
        process_vec(in, out, labels_i32, is64, i, c4);
    int j = i + half;
    if (i < half && j < n4)
        process_vec(in, out, labels_i32, is64, j, c4);
}

extern "C" void kernel_launch(void* const* d_in, const int* in_sizes, int n_in,
                              void* d_out, int out_size) {
    const float* logits = (const float*)d_in[0];
    const int32_t* labels = (const int32_t*)d_in[1];
    float* out = (float*)d_out;

    int total = in_sizes[0];      // B*C = 25,600,000
    int B = in_sizes[1];          // 256
    int C = total / B;            // 100,000 (divisible by 4)

    int n4 = total / 4;           // 6,400,000 vec4s
    int c4 = C / 4;               // 25,000 vec4s per row
    int half = (n4 + 1) / 2;      // ILP=2: each thread does i and i+half

    int threads = 256;
    int blocks = (half + threads - 1) / threads;
    arcface_fused_kernel<<<blocks, threads>>>(
        (const float4*)logits, labels, (float4*)out, n4, c4, half);
}